// round 2
// baseline (speedup 1.0000x reference)
#include <cuda_runtime.h>
#include <math.h>

#define BB 4
#define LQ 1024
#define LK 2048
#define EE 768
#define HH 16
#define HD 48
#define MQ (BB*LQ)   /* 4096 */
#define MK (BB*LK)   /* 8192 */

// ---------------- static scratch (device globals: allowed) ----------------
__device__ float g_qp[MQ*EE];                       // 12.6 MB
__device__ float g_kp[MK*EE];                       // 25.2 MB
__device__ float g_vp[MK*EE];                       // 25.2 MB
__device__ float g_scores[(size_t)BB*HH*LQ*LK];     // 512 MB
__device__ float g_ctx[MQ*EE];                      // 12.6 MB
__device__ float g_attnout[MQ*EE];                  // 12.6 MB
__device__ float g_qmean[BB*EE];
__device__ float g_kmean[BB*EE];
__device__ float g_sf[BB];
__device__ float g_gv[BB];

// ---------------- mean over sequence axis ----------------
__global__ void mean_kernel(const float* __restrict__ x, int L, int which) {
    int idx = blockIdx.x * blockDim.x + threadIdx.x;   // over BB*EE
    if (idx >= BB * EE) return;
    int b = idx / EE, e = idx % EE;
    const float* p = x + (size_t)b * L * EE + e;
    float s = 0.f;
    for (int l = 0; l < L; l++) s += p[(size_t)l * EE];
    float* dst = which ? g_kmean : g_qmean;
    dst[idx] = s / (float)L;
}

// ---------------- tiny controller MLP (one block per batch) ----------------
__global__ void mlp_kernel(const float* __restrict__ Wp1, const float* __restrict__ bp1,
                           const float* __restrict__ Wp2, const float* __restrict__ bp2,
                           const float* __restrict__ Wp3, const float* __restrict__ bp3,
                           float* __restrict__ out_tail) {
    int b = blockIdx.x;
    int t = threadIdx.x;           // 768 threads
    __shared__ float pin[2*EE];
    __shared__ float sh1[EE];
    __shared__ float sh2[EE/2];
    __shared__ float spred[3];
    pin[t]      = g_qmean[b*EE + t];
    pin[EE + t] = g_kmean[b*EE + t];
    __syncthreads();
    {
        float acc = bp1[t];
        const float* w = Wp1 + (size_t)t * (2*EE);
        for (int j = 0; j < 2*EE; j++) acc = fmaf(pin[j], w[j], acc);
        sh1[t] = fmaxf(acc, 0.f);
    }
    __syncthreads();
    if (t < EE/2) {
        float acc = bp2[t];
        const float* w = Wp2 + (size_t)t * EE;
        for (int j = 0; j < EE; j++) acc = fmaf(sh1[j], w[j], acc);
        sh2[t] = fmaxf(acc, 0.f);
    }
    __syncthreads();
    if (t < 3) {
        float acc = bp3[t];
        const float* w = Wp3 + t * (EE/2);
        for (int j = 0; j < EE/2; j++) acc = fmaf(sh2[j], w[j], acc);
        spred[t] = acc;
    }
    __syncthreads();
    if (t == 0) {
        float s0 = 1.f / (1.f + expf(-spred[0]));
        float nh = rintf(s0 * (float)(HH - 1) + 1.f);     // round-half-even, matches jnp.round
        float sf = (1.f / (1.f + expf(-spred[1]))) * 0.5f + 0.5f;
        float gv = 1.f / (1.f + expf(-spred[2]));
        g_sf[b] = sf; g_gv[b] = gv;
        out_tail[b]        = nh;
        out_tail[BB + b]   = sf;
        out_tail[2*BB + b] = gv;
    }
}

// ---------------- C[M,N] = A[M,K] @ W[N,K]^T + bias[N] ----------------
__global__ __launch_bounds__(256)
void gemm_abt_kernel(const float* __restrict__ A, const float* __restrict__ W,
                     const float* __restrict__ bias, float* __restrict__ C,
                     int M, int N, int K) {
    const int BM = 64, BN = 64, BK = 16;
    __shared__ float As[BK][BM + 1];
    __shared__ float Ws[BK][BN + 1];
    int tx = threadIdx.x, ty = threadIdx.y;
    int tid = ty * 16 + tx;
    int m0 = blockIdx.y * BM, n0 = blockIdx.x * BN;
    float c[4][4] = {};
    for (int k0 = 0; k0 < K; k0 += BK) {
        #pragma unroll
        for (int i = tid; i < BM * BK; i += 256) {
            int m = i >> 4, kk = i & 15;
            As[kk][m] = A[(size_t)(m0 + m) * K + k0 + kk];
            Ws[kk][m] = W[(size_t)(n0 + m) * K + k0 + kk];
        }
        __syncthreads();
        #pragma unroll
        for (int kk = 0; kk < BK; kk++) {
            float a[4], bv[4];
            #pragma unroll
            for (int i = 0; i < 4; i++) a[i] = As[kk][ty*4 + i];
            #pragma unroll
            for (int j = 0; j < 4; j++) bv[j] = Ws[kk][tx*4 + j];
            #pragma unroll
            for (int i = 0; i < 4; i++)
                #pragma unroll
                for (int j = 0; j < 4; j++)
                    c[i][j] = fmaf(a[i], bv[j], c[i][j]);
        }
        __syncthreads();
    }
    #pragma unroll
    for (int i = 0; i < 4; i++) {
        int m = m0 + ty*4 + i;
        #pragma unroll
        for (int j = 0; j < 4; j++) {
            int n = n0 + tx*4 + j;
            C[(size_t)m * N + n] = c[i][j] + bias[n];
        }
    }
}

// ---------------- scores[b,h,q,k] = (q·k)/sqrt(HD), masked ----------------
__global__ __launch_bounds__(256)
void scores_kernel(const unsigned char* __restrict__ mask) {
    int bh = blockIdx.z;                 // b*HH + h
    int b = bh >> 4, h = bh & 15;
    __shared__ float Qs[HD][64 + 1];
    __shared__ float Ks[HD][64 + 1];
    int tx = threadIdx.x, ty = threadIdx.y;
    int tid = ty * 16 + tx;
    int q0 = blockIdx.y * 64, k0 = blockIdx.x * 64;
    for (int i = tid; i < 64 * HD; i += 256) {
        int r = i / HD, d = i % HD;
        Qs[d][r] = g_qp[(size_t)(b*LQ + q0 + r) * EE + h*HD + d];
        Ks[d][r] = g_kp[(size_t)(b*LK + k0 + r) * EE + h*HD + d];
    }
    __syncthreads();
    float c[4][4] = {};
    #pragma unroll 8
    for (int d = 0; d < HD; d++) {
        float a[4], bv[4];
        #pragma unroll
        for (int i = 0; i < 4; i++) a[i] = Qs[d][ty*4 + i];
        #pragma unroll
        for (int j = 0; j < 4; j++) bv[j] = Ks[d][tx*4 + j];
        #pragma unroll
        for (int i = 0; i < 4; i++)
            #pragma unroll
            for (int j = 0; j < 4; j++)
                c[i][j] = fmaf(a[i], bv[j], c[i][j]);
    }
    const float scale = 0.14433756729740643f;   // 1/sqrt(48)
    #pragma unroll
    for (int i = 0; i < 4; i++) {
        int q = q0 + ty*4 + i;
        float* row = g_scores + ((size_t)bh * LQ + q) * LK;
        #pragma unroll
        for (int j = 0; j < 4; j++) {
            int k = k0 + tx*4 + j;
            float s = c[i][j] * scale;
            if (mask[b*LK + k]) s = -1e30f;
            row[k] = s;
        }
    }
}

// ---------------- in-place row softmax over LK ----------------
__global__ __launch_bounds__(256)
void softmax_kernel() {
    int row = blockIdx.x;                    // over BB*HH*LQ
    float* p = g_scores + (size_t)row * LK;
    __shared__ float sbuf[8];
    __shared__ float sbuf2[8];
    int tid = threadIdx.x;
    float vals[8];
    float vmax = -3.4e38f;
    #pragma unroll
    for (int i = 0; i < 8; i++) { vals[i] = p[tid + i*256]; vmax = fmaxf(vmax, vals[i]); }
    #pragma unroll
    for (int o = 16; o > 0; o >>= 1) vmax = fmaxf(vmax, __shfl_xor_sync(0xffffffffu, vmax, o));
    if ((tid & 31) == 0) sbuf[tid >> 5] = vmax;
    __syncthreads();
    float m = sbuf[0];
    #pragma unroll
    for (int i = 1; i < 8; i++) m = fmaxf(m, sbuf[i]);
    float s = 0.f;
    #pragma unroll
    for (int i = 0; i < 8; i++) { vals[i] = expf(vals[i] - m); s += vals[i]; }
    #pragma unroll
    for (int o = 16; o > 0; o >>= 1) s += __shfl_xor_sync(0xffffffffu, s, o);
    if ((tid & 31) == 0) sbuf2[tid >> 5] = s;
    __syncthreads();
    float tot = 0.f;
    #pragma unroll
    for (int i = 0; i < 8; i++) tot += sbuf2[i];
    float inv = 1.f / tot;
    #pragma unroll
    for (int i = 0; i < 8; i++) p[tid + i*256] = vals[i] * inv;
}

// ---------------- ctx[b,q,h*HD+d] = sum_k attn * v ----------------
__global__ __launch_bounds__(256)
void ctx_kernel() {
    int qt = blockIdx.x;        // 0..15
    int bh = blockIdx.y;        // 0..63
    int b = bh >> 4, h = bh & 15;
    __shared__ float As[64][33];
    __shared__ float Vs[32][HD + 1];
    int tx = threadIdx.x, ty = threadIdx.y;
    int tid = ty * 16 + tx;
    int q0 = qt * 64;
    float c[4][3] = {};
    const float* srow = g_scores + ((size_t)bh * LQ + q0) * LK;
    const float* vbase = g_vp + (size_t)b * LK * EE + h * HD;
    for (int k0 = 0; k0 < LK; k0 += 32) {
        #pragma unroll
        for (int i = tid; i < 64*32; i += 256) {
            int r = i >> 5, kk = i & 31;
            As[r][kk] = srow[(size_t)r * LK + k0 + kk];
        }
        #pragma unroll
        for (int i = tid; i < 32*HD; i += 256) {
            int kk = i / HD, d = i % HD;
            Vs[kk][d] = vbase[(size_t)(k0 + kk) * EE + d];
        }
        __syncthreads();
        #pragma unroll
        for (int kk = 0; kk < 32; kk++) {
            float a[4], bv[3];
            #pragma unroll
            for (int i = 0; i < 4; i++) a[i] = As[ty*4 + i][kk];
            #pragma unroll
            for (int j = 0; j < 3; j++) bv[j] = Vs[kk][tx*3 + j];
            #pragma unroll
            for (int i = 0; i < 4; i++)
                #pragma unroll
                for (int j = 0; j < 3; j++)
                    c[i][j] = fmaf(a[i], bv[j], c[i][j]);
        }
        __syncthreads();
    }
    float* cbase = g_ctx + (size_t)(b*LQ + q0) * EE + h * HD;
    #pragma unroll
    for (int i = 0; i < 4; i++)
        #pragma unroll
        for (int j = 0; j < 3; j++)
            cbase[(size_t)(ty*4 + i) * EE + tx*3 + j] = c[i][j];
}

// ---------------- attn_weights = mean over heads ----------------
__global__ void attnmean_kernel(float* __restrict__ aw) {
    size_t idx = (size_t)blockIdx.x * blockDim.x + threadIdx.x;   // float4 index
    const size_t nPer = (size_t)LQ * LK / 4;
    if (idx >= (size_t)BB * nPer) return;
    size_t b = idx / nPer, r = idx % nPer;
    const float4* base = (const float4*)g_scores;
    float4 s = make_float4(0.f, 0.f, 0.f, 0.f);
    #pragma unroll
    for (int h = 0; h < HH; h++) {
        float4 v = base[(b*HH + h) * nPer + r];
        s.x += v.x; s.y += v.y; s.z += v.z; s.w += v.w;
    }
    const float inv = 1.f / (float)HH;
    s.x *= inv; s.y *= inv; s.z *= inv; s.w *= inv;
    ((float4*)aw)[idx] = s;
}

// ---------------- gate + residual + LayerNorm ----------------
__global__ __launch_bounds__(256)
void final_kernel(const float* __restrict__ query, const float* __restrict__ ln_g,
                  const float* __restrict__ ln_b, float* __restrict__ out) {
    int row = blockIdx.x;              // over BB*LQ
    int b = row / LQ;
    float sf = g_sf[b], gv = g_gv[b];
    const float* qrow = query + (size_t)row * EE;
    const float* arow = g_attnout + (size_t)row * EE;
    __shared__ float sx[EE];
    __shared__ float sbuf[8], sbuf2[8];
    int tid = threadIdx.x;
    float lsum = 0.f, lsq = 0.f;
    for (int i = tid; i < EE; i += 256) {
        float qv = qrow[i];
        float gated = qv * (1.f - gv) + arow[i] * sf * gv;
        float x = qv + gated;
        sx[i] = x; lsum += x; lsq += x * x;
    }
    #pragma unroll
    for (int o = 16; o > 0; o >>= 1) {
        lsum += __shfl_xor_sync(0xffffffffu, lsum, o);
        lsq  += __shfl_xor_sync(0xffffffffu, lsq, o);
    }
    if ((tid & 31) == 0) { sbuf[tid >> 5] = lsum; sbuf2[tid >> 5] = lsq; }
    __syncthreads();
    float ts = 0.f, tq = 0.f;
    #pragma unroll
    for (int i = 0; i < 8; i++) { ts += sbuf[i]; tq += sbuf2[i]; }
    float mu = ts / (float)EE;
    float var = tq / (float)EE - mu * mu;
    float inv = rsqrtf(var + 1e-5f);
    float* orow = out + (size_t)row * EE;
    for (int i = tid; i < EE; i += 256)
        orow[i] = (sx[i] - mu) * inv * ln_g[i] + ln_b[i];
}

// ---------------- launch ----------------
extern "C" void kernel_launch(void* const* d_in, const int* in_sizes, int n_in,
                              void* d_out, int out_size) {
    const float* query = (const float*)d_in[0];
    const float* key   = (const float*)d_in[1];
    const float* value = (const float*)d_in[2];
    const unsigned char* mask = (const unsigned char*)d_in[3];
    const float* Wp1 = (const float*)d_in[4];
    const float* bp1 = (const float*)d_in[5];
    const float* Wp2 = (const float*)d_in[6];
    const float* bp2 = (const float*)d_in[7];
    const float* Wp3 = (const float*)d_in[8];
    const float* bp3 = (const float*)d_in[9];
    const float* inw = (const float*)d_in[10];
    const float* inb = (const float*)d_in[11];
    const float* outw = (const float*)d_in[12];
    const float* outb = (const float*)d_in[13];
    const float* lng = (const float*)d_in[14];
    const float* lnb = (const float*)d_in[15];

    float* out = (float*)d_out;
    float* out_output = out;                                   // (B,Lq,E)
    float* out_aw = out + (size_t)BB * LQ * EE;                // (B,Lq,Lk)
    float* out_tail = out_aw + (size_t)BB * LQ * LK;           // nh[4], sf[4], gv[4]

    float *qp, *kp, *vp, *ctx, *aout;
    cudaGetSymbolAddress((void**)&qp, g_qp);
    cudaGetSymbolAddress((void**)&kp, g_kp);
    cudaGetSymbolAddress((void**)&vp, g_vp);
    cudaGetSymbolAddress((void**)&ctx, g_ctx);
    cudaGetSymbolAddress((void**)&aout, g_attnout);

    // 1) means
    mean_kernel<<<(BB*EE + 255)/256, 256>>>(query, LQ, 0);
    mean_kernel<<<(BB*EE + 255)/256, 256>>>(key,   LK, 1);
    // 2) controller MLP (writes tail of d_out and g_sf/g_gv)
    mlp_kernel<<<BB, EE>>>(Wp1, bp1, Wp2, bp2, Wp3, bp3, out_tail);
    // 3) Q/K/V projections
    dim3 blk(16, 16);
    gemm_abt_kernel<<<dim3(EE/64, MQ/64), blk>>>(query, inw,            inb,        qp,  MQ, EE, EE);
    gemm_abt_kernel<<<dim3(EE/64, MK/64), blk>>>(key,   inw + EE*EE,    inb + EE,   kp,  MK, EE, EE);
    gemm_abt_kernel<<<dim3(EE/64, MK/64), blk>>>(value, inw + 2*EE*EE,  inb + 2*EE, vp,  MK, EE, EE);
    // 4) scores
    scores_kernel<<<dim3(LK/64, LQ/64, BB*HH), blk>>>(mask);
    // 5) softmax (in place)
    softmax_kernel<<<BB*HH*LQ, 256>>>();
    // 6) ctx
    ctx_kernel<<<dim3(LQ/64, BB*HH), blk>>>();
    // 7) out projection
    gemm_abt_kernel<<<dim3(EE/64, MQ/64), blk>>>(ctx, outw, outb, aout, MQ, EE, EE);
    // 8) attn_weights = head mean
    {
        size_t n4 = (size_t)BB * LQ * LK / 4;
        attnmean_kernel<<<(unsigned)((n4 + 255)/256), 256>>>(out_aw);
    }
    // 9) gate + residual + LayerNorm
    final_kernel<<<BB*LQ, 256>>>(query, lng, lnb, out_output);
}

// round 3
// speedup vs baseline: 1.4212x; 1.4212x over previous
#include <cuda_runtime.h>
#include <math.h>

#define BB 4
#define LQ 1024
#define LK 2048
#define EE 768
#define HH 16
#define HD 48
#define MQ (BB*LQ)   /* 4096 */
#define MK (BB*LK)   /* 8192 */

// ---------------- static scratch ----------------
__device__ float g_qp[MQ*EE];
__device__ float g_kp[MK*EE];
__device__ float g_vp[MK*EE];
__device__ float g_scores[(size_t)BB*HH*LQ*LK];     // 512 MB raw masked/scaled scores
__device__ float g_ctx[MQ*EE];
__device__ float g_attnout[MQ*EE];
__device__ float g_qmean[BB*EE];
__device__ float g_kmean[BB*EE];
__device__ float g_sf[BB];
__device__ float g_gv[BB];
__device__ float g_rowm[BB*HH*LQ];
__device__ float g_rowinv[BB*HH*LQ];

// ---------------- mean over sequence axis ----------------
__global__ void mean_kernel(const float* __restrict__ x, int L, int which) {
    int idx = blockIdx.x * blockDim.x + threadIdx.x;
    if (idx >= BB * EE) return;
    int b = idx / EE, e = idx % EE;
    const float* p = x + (size_t)b * L * EE + e;
    float s = 0.f;
    for (int l = 0; l < L; l++) s += p[(size_t)l * EE];
    float* dst = which ? g_kmean : g_qmean;
    dst[idx] = s / (float)L;
}

// ---------------- controller MLP ----------------
__global__ void mlp_kernel(const float* __restrict__ Wp1, const float* __restrict__ bp1,
                           const float* __restrict__ Wp2, const float* __restrict__ bp2,
                           const float* __restrict__ Wp3, const float* __restrict__ bp3,
                           float* __restrict__ out_tail) {
    int b = blockIdx.x;
    int t = threadIdx.x;           // 768
    __shared__ float pin[2*EE];
    __shared__ float sh1[EE];
    __shared__ float sh2[EE/2];
    __shared__ float spred[3];
    pin[t]      = g_qmean[b*EE + t];
    pin[EE + t] = g_kmean[b*EE + t];
    __syncthreads();
    {
        float acc = bp1[t];
        const float* w = Wp1 + (size_t)t * (2*EE);
        for (int j = 0; j < 2*EE; j++) acc = fmaf(pin[j], w[j], acc);
        sh1[t] = fmaxf(acc, 0.f);
    }
    __syncthreads();
    if (t < EE/2) {
        float acc = bp2[t];
        const float* w = Wp2 + (size_t)t * EE;
        for (int j = 0; j < EE; j++) acc = fmaf(sh1[j], w[j], acc);
        sh2[t] = fmaxf(acc, 0.f);
    }
    __syncthreads();
    if (t < 3) {
        float acc = bp3[t];
        const float* w = Wp3 + t * (EE/2);
        for (int j = 0; j < EE/2; j++) acc = fmaf(sh2[j], w[j], acc);
        spred[t] = acc;
    }
    __syncthreads();
    if (t == 0) {
        float s0 = 1.f / (1.f + expf(-spred[0]));
        float nh = rintf(s0 * (float)(HH - 1) + 1.f);
        float sf = (1.f / (1.f + expf(-spred[1]))) * 0.5f + 0.5f;
        float gv = 1.f / (1.f + expf(-spred[2]));
        g_sf[b] = sf; g_gv[b] = gv;
        out_tail[b]        = nh;
        out_tail[BB + b]   = sf;
        out_tail[2*BB + b] = gv;
    }
}

// ---------------- C[M,N] = A[M,K] @ W[N,K]^T + bias, 128x128x8 double-buffered ----------------
__global__ __launch_bounds__(256)
void gemm128_kernel(const float* __restrict__ A, const float* __restrict__ W,
                    const float* __restrict__ bias, float* __restrict__ C,
                    int M, int N, int K) {
    __shared__ float As[2][8][128];
    __shared__ float Bs[2][8][128];
    const int tid = threadIdx.x;
    const int tx = tid & 15, ty = tid >> 4;
    const int m0 = blockIdx.y * 128, n0 = blockIdx.x * 128;
    const int lr = tid >> 1, lc = (tid & 1) * 4;
    const float* Ap = A + (size_t)(m0 + lr) * K + lc;
    const float* Wp = W + (size_t)(n0 + lr) * K + lc;
    float4 av = *(const float4*)Ap;
    float4 wv = *(const float4*)Wp;
    float acc[8][8] = {};
    const int ktiles = K >> 3;
    int buf = 0;
    for (int t = 0; t < ktiles; t++) {
        As[buf][lc+0][lr] = av.x; As[buf][lc+1][lr] = av.y;
        As[buf][lc+2][lr] = av.z; As[buf][lc+3][lr] = av.w;
        Bs[buf][lc+0][lr] = wv.x; Bs[buf][lc+1][lr] = wv.y;
        Bs[buf][lc+2][lr] = wv.z; Bs[buf][lc+3][lr] = wv.w;
        __syncthreads();
        if (t + 1 < ktiles) {
            av = *(const float4*)(Ap + (t+1)*8);
            wv = *(const float4*)(Wp + (t+1)*8);
        }
        #pragma unroll
        for (int kk = 0; kk < 8; kk++) {
            float4 a0 = *(const float4*)&As[buf][kk][ty*4];
            float4 a1 = *(const float4*)&As[buf][kk][64 + ty*4];
            float4 b0 = *(const float4*)&Bs[buf][kk][tx*4];
            float4 b1 = *(const float4*)&Bs[buf][kk][64 + tx*4];
            float a[8] = {a0.x,a0.y,a0.z,a0.w,a1.x,a1.y,a1.z,a1.w};
            float bvv[8] = {b0.x,b0.y,b0.z,b0.w,b1.x,b1.y,b1.z,b1.w};
            #pragma unroll
            for (int i = 0; i < 8; i++)
                #pragma unroll
                for (int j = 0; j < 8; j++)
                    acc[i][j] = fmaf(a[i], bvv[j], acc[i][j]);
        }
        buf ^= 1;
    }
    #pragma unroll
    for (int i = 0; i < 8; i++) {
        int m = m0 + ((i < 4) ? (ty*4 + i) : (64 + ty*4 + i - 4));
        #pragma unroll
        for (int jh = 0; jh < 2; jh++) {
            int n = n0 + jh*64 + tx*4;
            float4 o;
            o.x = acc[i][jh*4+0] + bias[n+0];
            o.y = acc[i][jh*4+1] + bias[n+1];
            o.z = acc[i][jh*4+2] + bias[n+2];
            o.w = acc[i][jh*4+3] + bias[n+3];
            *(float4*)&C[(size_t)m * N + n] = o;
        }
    }
}

// ---------------- scores 128x128 tiles over K=48, mask+scale fused ----------------
__global__ __launch_bounds__(256)
void scores128_kernel(const unsigned char* __restrict__ mask) {
    const int bh = blockIdx.z, b = bh >> 4, h = bh & 15;
    __shared__ float As[2][8][128];
    __shared__ float Bs[2][8][128];
    const int tid = threadIdx.x;
    const int tx = tid & 15, ty = tid >> 4;
    const int q0 = blockIdx.y * 128, k0 = blockIdx.x * 128;
    const int lr = tid >> 1, lc = (tid & 1) * 4;
    const float* Ap = g_qp + (size_t)(b*LQ + q0 + lr) * EE + h*HD + lc;
    const float* Bp = g_kp + (size_t)(b*LK + k0 + lr) * EE + h*HD + lc;
    float4 av = *(const float4*)Ap;
    float4 wv = *(const float4*)Bp;
    float acc[8][8] = {};
    int buf = 0;
    #pragma unroll
    for (int t = 0; t < 6; t++) {           // K = 48 = 6 * 8
        As[buf][lc+0][lr] = av.x; As[buf][lc+1][lr] = av.y;
        As[buf][lc+2][lr] = av.z; As[buf][lc+3][lr] = av.w;
        Bs[buf][lc+0][lr] = wv.x; Bs[buf][lc+1][lr] = wv.y;
        Bs[buf][lc+2][lr] = wv.z; Bs[buf][lc+3][lr] = wv.w;
        __syncthreads();
        if (t + 1 < 6) {
            av = *(const float4*)(Ap + (t+1)*8);
            wv = *(const float4*)(Bp + (t+1)*8);
        }
        #pragma unroll
        for (int kk = 0; kk < 8; kk++) {
            float4 a0 = *(const float4*)&As[buf][kk][ty*4];
            float4 a1 = *(const float4*)&As[buf][kk][64 + ty*4];
            float4 b0 = *(const float4*)&Bs[buf][kk][tx*4];
            float4 b1 = *(const float4*)&Bs[buf][kk][64 + tx*4];
            float a[8] = {a0.x,a0.y,a0.z,a0.w,a1.x,a1.y,a1.z,a1.w};
            float bvv[8] = {b0.x,b0.y,b0.z,b0.w,b1.x,b1.y,b1.z,b1.w};
            #pragma unroll
            for (int i = 0; i < 8; i++)
                #pragma unroll
                for (int j = 0; j < 8; j++)
                    acc[i][j] = fmaf(a[i], bvv[j], acc[i][j]);
        }
        buf ^= 1;
    }
    const float scale = 0.14433756729740643f;   // 1/sqrt(48)
    float* sbase = g_scores + (size_t)bh * LQ * LK;
    #pragma unroll
    for (int i = 0; i < 8; i++) {
        int q = q0 + ((i < 4) ? (ty*4 + i) : (64 + ty*4 + i - 4));
        #pragma unroll
        for (int jh = 0; jh < 2; jh++) {
            int k = k0 + jh*64 + tx*4;
            const unsigned char* mp = mask + b*LK + k;
            float4 o;
            o.x = mp[0] ? -1e30f : acc[i][jh*4+0] * scale;
            o.y = mp[1] ? -1e30f : acc[i][jh*4+1] * scale;
            o.z = mp[2] ? -1e30f : acc[i][jh*4+2] * scale;
            o.w = mp[3] ? -1e30f : acc[i][jh*4+3] * scale;
            *(float4*)&sbase[(size_t)q * LK + k] = o;
        }
    }
}

// ---------------- per-row softmax stats (max, 1/sum) ----------------
__global__ __launch_bounds__(256)
void rowstat_kernel() {
    int row = blockIdx.x;                    // BB*HH*LQ
    const float4* p = (const float4*)(g_scores + (size_t)row * LK);
    int tid = threadIdx.x;
    float4 v0 = p[tid];
    float4 v1 = p[tid + 256];
    float vmax = fmaxf(fmaxf(fmaxf(v0.x, v0.y), fmaxf(v0.z, v0.w)),
                       fmaxf(fmaxf(v1.x, v1.y), fmaxf(v1.z, v1.w)));
    __shared__ float sb[8], sb2[8];
    #pragma unroll
    for (int o = 16; o > 0; o >>= 1) vmax = fmaxf(vmax, __shfl_xor_sync(0xffffffffu, vmax, o));
    if ((tid & 31) == 0) sb[tid >> 5] = vmax;
    __syncthreads();
    float m = sb[0];
    #pragma unroll
    for (int i = 1; i < 8; i++) m = fmaxf(m, sb[i]);
    float s = __expf(v0.x - m) + __expf(v0.y - m) + __expf(v0.z - m) + __expf(v0.w - m)
            + __expf(v1.x - m) + __expf(v1.y - m) + __expf(v1.z - m) + __expf(v1.w - m);
    #pragma unroll
    for (int o = 16; o > 0; o >>= 1) s += __shfl_xor_sync(0xffffffffu, s, o);
    if ((tid & 31) == 0) sb2[tid >> 5] = s;
    __syncthreads();
    if (tid == 0) {
        float tot = 0.f;
        #pragma unroll
        for (int i = 0; i < 8; i++) tot += sb2[i];
        g_rowm[row] = m;
        g_rowinv[row] = 1.f / tot;
    }
}

// ---------------- ctx: exp-normalize on the fly, 128q x 48d x 32k tiles ----------------
__global__ __launch_bounds__(256)
void ctx_kernel() {
    const int bh = blockIdx.y, b = bh >> 4, h = bh & 15;
    const int q0 = blockIdx.x * 128;
    __shared__ float As[32][128];
    __shared__ float Vs[32][48];
    const int tid = threadIdx.x;
    const int tx = tid & 15, ty = tid >> 4;
    const int lq = tid >> 1, lkc = (tid & 1) * 16;
    const float* srow = g_scores + ((size_t)bh * LQ + q0) * LK;
    const float* vbase = g_vp + (size_t)b * LK * EE + h * HD;
    const float rm  = g_rowm[bh*LQ + q0 + lq];
    const float rin = g_rowinv[bh*LQ + q0 + lq];
    float acc[8][3] = {};
    for (int kb = 0; kb < LK; kb += 32) {
        const float4* sp = (const float4*)(srow + (size_t)lq * LK + kb + lkc);
        #pragma unroll
        for (int c4 = 0; c4 < 4; c4++) {
            float4 v = sp[c4];
            int kk = lkc + c4*4;
            As[kk+0][lq] = __expf(v.x - rm) * rin;
            As[kk+1][lq] = __expf(v.y - rm) * rin;
            As[kk+2][lq] = __expf(v.z - rm) * rin;
            As[kk+3][lq] = __expf(v.w - rm) * rin;
        }
        for (int i = tid; i < 32*48; i += 256) {
            int kk = i / 48, d = i - kk*48;
            Vs[kk][d] = vbase[(size_t)(kb + kk) * EE + d];
        }
        __syncthreads();
        #pragma unroll
        for (int kk = 0; kk < 32; kk++) {
            float4 a0 = *(const float4*)&As[kk][ty*4];
            float4 a1 = *(const float4*)&As[kk][64 + ty*4];
            float a[8] = {a0.x,a0.y,a0.z,a0.w,a1.x,a1.y,a1.z,a1.w};
            float w0 = Vs[kk][tx*3+0], w1 = Vs[kk][tx*3+1], w2 = Vs[kk][tx*3+2];
            #pragma unroll
            for (int i = 0; i < 8; i++) {
                acc[i][0] = fmaf(a[i], w0, acc[i][0]);
                acc[i][1] = fmaf(a[i], w1, acc[i][1]);
                acc[i][2] = fmaf(a[i], w2, acc[i][2]);
            }
        }
        __syncthreads();
    }
    float* cb = g_ctx + (size_t)(b*LQ + q0) * EE + h*HD + tx*3;
    #pragma unroll
    for (int i = 0; i < 8; i++) {
        int r = (i < 4) ? (ty*4 + i) : (64 + ty*4 + i - 4);
        cb[(size_t)r*EE + 0] = acc[i][0];
        cb[(size_t)r*EE + 1] = acc[i][1];
        cb[(size_t)r*EE + 2] = acc[i][2];
    }
}

// ---------------- attn_weights = head mean of normalized probs ----------------
__global__ void attnmean_kernel(float* __restrict__ aw) {
    size_t idx = (size_t)blockIdx.x * blockDim.x + threadIdx.x;   // float4 index
    const size_t nPer = (size_t)LQ * (LK/4);
    if (idx >= (size_t)BB * nPer) return;
    size_t b = idx / nPer, rem = idx % nPer;
    int q = (int)(rem / (LK/4));
    size_t k4 = rem % (LK/4);
    const float4* base = (const float4*)g_scores;
    float4 s = make_float4(0.f, 0.f, 0.f, 0.f);
    #pragma unroll
    for (int h = 0; h < HH; h++) {
        int row = ((int)b*HH + h)*LQ + q;
        float m = g_rowm[row], inv = g_rowinv[row];
        float4 v = base[(size_t)row * (LK/4) + k4];
        s.x += __expf(v.x - m) * inv;
        s.y += __expf(v.y - m) * inv;
        s.z += __expf(v.z - m) * inv;
        s.w += __expf(v.w - m) * inv;
    }
    const float invH = 1.f / (float)HH;
    s.x *= invH; s.y *= invH; s.z *= invH; s.w *= invH;
    ((float4*)aw)[idx] = s;
}

// ---------------- gate + residual + LayerNorm ----------------
__global__ __launch_bounds__(256)
void final_kernel(const float* __restrict__ query, const float* __restrict__ ln_g,
                  const float* __restrict__ ln_b, float* __restrict__ out) {
    int row = blockIdx.x;
    int b = row / LQ;
    float sf = g_sf[b], gv = g_gv[b];
    const float* qrow = query + (size_t)row * EE;
    const float* arow = g_attnout + (size_t)row * EE;
    __shared__ float sx[EE];
    __shared__ float sbuf[8], sbuf2[8];
    int tid = threadIdx.x;
    float lsum = 0.f, lsq = 0.f;
    for (int i = tid; i < EE; i += 256) {
        float qv = qrow[i];
        float gated = qv * (1.f - gv) + arow[i] * sf * gv;
        float x = qv + gated;
        sx[i] = x; lsum += x; lsq += x * x;
    }
    #pragma unroll
    for (int o = 16; o > 0; o >>= 1) {
        lsum += __shfl_xor_sync(0xffffffffu, lsum, o);
        lsq  += __shfl_xor_sync(0xffffffffu, lsq, o);
    }
    if ((tid & 31) == 0) { sbuf[tid >> 5] = lsum; sbuf2[tid >> 5] = lsq; }
    __syncthreads();
    float ts = 0.f, tq = 0.f;
    #pragma unroll
    for (int i = 0; i < 8; i++) { ts += sbuf[i]; tq += sbuf2[i]; }
    float mu = ts / (float)EE;
    float var = tq / (float)EE - mu * mu;
    float inv = rsqrtf(var + 1e-5f);
    float* orow = out + (size_t)row * EE;
    for (int i = tid; i < EE; i += 256)
        orow[i] = (sx[i] - mu) * inv * ln_g[i] + ln_b[i];
}

// ---------------- launch ----------------
extern "C" void kernel_launch(void* const* d_in, const int* in_sizes, int n_in,
                              void* d_out, int out_size) {
    const float* query = (const float*)d_in[0];
    const float* key   = (const float*)d_in[1];
    const float* value = (const float*)d_in[2];
    const unsigned char* mask = (const unsigned char*)d_in[3];
    const float* Wp1 = (const float*)d_in[4];
    const float* bp1 = (const float*)d_in[5];
    const float* Wp2 = (const float*)d_in[6];
    const float* bp2 = (const float*)d_in[7];
    const float* Wp3 = (const float*)d_in[8];
    const float* bp3 = (const float*)d_in[9];
    const float* inw = (const float*)d_in[10];
    const float* inb = (const float*)d_in[11];
    const float* outw = (const float*)d_in[12];
    const float* outb = (const float*)d_in[13];
    const float* lng = (const float*)d_in[14];
    const float* lnb = (const float*)d_in[15];

    float* out = (float*)d_out;
    float* out_output = out;
    float* out_aw = out + (size_t)BB * LQ * EE;
    float* out_tail = out_aw + (size_t)BB * LQ * LK;

    float *qp, *kp, *vp, *ctx, *aout;
    cudaGetSymbolAddress((void**)&qp, g_qp);
    cudaGetSymbolAddress((void**)&kp, g_kp);
    cudaGetSymbolAddress((void**)&vp, g_vp);
    cudaGetSymbolAddress((void**)&ctx, g_ctx);
    cudaGetSymbolAddress((void**)&aout, g_attnout);

    mean_kernel<<<(BB*EE + 255)/256, 256>>>(query, LQ, 0);
    mean_kernel<<<(BB*EE + 255)/256, 256>>>(key,   LK, 1);
    mlp_kernel<<<BB, EE>>>(Wp1, bp1, Wp2, bp2, Wp3, bp3, out_tail);

    gemm128_kernel<<<dim3(EE/128, MQ/128), 256>>>(query, inw,           inb,        qp,  MQ, EE, EE);
    gemm128_kernel<<<dim3(EE/128, MK/128), 256>>>(key,   inw + EE*EE,   inb + EE,   kp,  MK, EE, EE);
    gemm128_kernel<<<dim3(EE/128, MK/128), 256>>>(value, inw + 2*EE*EE, inb + 2*EE, vp,  MK, EE, EE);

    scores128_kernel<<<dim3(LK/128, LQ/128, BB*HH), 256>>>(mask);
    rowstat_kernel<<<BB*HH*LQ, 256>>>();
    ctx_kernel<<<dim3(LQ/128, BB*HH), 256>>>();

    gemm128_kernel<<<dim3(EE/128, MQ/128), 256>>>(ctx, outw, outb, aout, MQ, EE, EE);

    {
        size_t n4 = (size_t)BB * LQ * LK / 4;
        attnmean_kernel<<<(unsigned)((n4 + 255)/256), 256>>>(out_aw);
    }
    final_kernel<<<BB*LQ, 256>>>(query, lng, lnb, out_output);
}

// round 4
// speedup vs baseline: 1.6647x; 1.1713x over previous
#include <cuda_runtime.h>
#include <math.h>

#define BB 4
#define LQ 1024
#define LK 2048
#define EE 768
#define HH 16
#define HD 48
#define MQ (BB*LQ)
#define MK (BB*LK)
#define SPITCH 130   // smem row pitch (in 32-bit words) for 128-wide tiles

// ---------------- static scratch ----------------
__device__ float g_qp[MQ*EE];
__device__ float g_kp[MK*EE];
__device__ float g_vp[MK*EE];
__device__ float g_scores[(size_t)BB*HH*LQ*LK];
__device__ float g_ctx[MQ*EE];
__device__ float g_attnout[MQ*EE];
__device__ float g_qmean[BB*EE];
__device__ float g_kmean[BB*EE];
__device__ float g_sf[BB];
__device__ float g_gv[BB];
__device__ float g_rowm[BB*HH*LQ];
__device__ float g_rowinv[BB*HH*LQ];

// ---------------- tf32 helpers ----------------
__device__ __forceinline__ unsigned f2tf(float x) {
    unsigned r; asm("cvt.rna.tf32.f32 %0, %1;" : "=r"(r) : "f"(x)); return r;
}
__device__ __forceinline__ void mma_tf32(float* c, unsigned a0, unsigned a1, unsigned a2, unsigned a3,
                                         unsigned b0, unsigned b1) {
    asm volatile("mma.sync.aligned.m16n8k8.row.col.f32.tf32.tf32.f32 "
                 "{%0,%1,%2,%3},{%4,%5,%6,%7},{%8,%9},{%0,%1,%2,%3};"
                 : "+f"(c[0]), "+f"(c[1]), "+f"(c[2]), "+f"(c[3])
                 : "r"(a0), "r"(a1), "r"(a2), "r"(a3), "r"(b0), "r"(b1));
}

// ---------------- mean over sequence axis ----------------
__global__ void mean_kernel(const float* __restrict__ x, int L, int which) {
    int idx = blockIdx.x * blockDim.x + threadIdx.x;
    if (idx >= BB * EE) return;
    int b = idx / EE, e = idx % EE;
    const float* p = x + (size_t)b * L * EE + e;
    float s = 0.f;
    for (int l = 0; l < L; l++) s += p[(size_t)l * EE];
    (which ? g_kmean : g_qmean)[idx] = s / (float)L;
}

// ---------------- controller MLP ----------------
__global__ void mlp_kernel(const float* __restrict__ Wp1, const float* __restrict__ bp1,
                           const float* __restrict__ Wp2, const float* __restrict__ bp2,
                           const float* __restrict__ Wp3, const float* __restrict__ bp3,
                           float* __restrict__ out_tail) {
    int b = blockIdx.x;
    int t = threadIdx.x;
    __shared__ float pin[2*EE];
    __shared__ float sh1[EE];
    __shared__ float sh2[EE/2];
    __shared__ float spred[3];
    pin[t]      = g_qmean[b*EE + t];
    pin[EE + t] = g_kmean[b*EE + t];
    __syncthreads();
    {
        float acc = bp1[t];
        const float* w = Wp1 + (size_t)t * (2*EE);
        for (int j = 0; j < 2*EE; j++) acc = fmaf(pin[j], w[j], acc);
        sh1[t] = fmaxf(acc, 0.f);
    }
    __syncthreads();
    if (t < EE/2) {
        float acc = bp2[t];
        const float* w = Wp2 + (size_t)t * EE;
        for (int j = 0; j < EE; j++) acc = fmaf(sh1[j], w[j], acc);
        sh2[t] = fmaxf(acc, 0.f);
    }
    __syncthreads();
    if (t < 3) {
        float acc = bp3[t];
        const float* w = Wp3 + t * (EE/2);
        for (int j = 0; j < EE/2; j++) acc = fmaf(sh2[j], w[j], acc);
        spred[t] = acc;
    }
    __syncthreads();
    if (t == 0) {
        float s0 = 1.f / (1.f + expf(-spred[0]));
        float nh = rintf(s0 * (float)(HH - 1) + 1.f);
        float sf = (1.f / (1.f + expf(-spred[1]))) * 0.5f + 0.5f;
        float gv = 1.f / (1.f + expf(-spred[2]));
        g_sf[b] = sf; g_gv[b] = gv;
        out_tail[b]        = nh;
        out_tail[BB + b]   = sf;
        out_tail[2*BB + b] = gv;
    }
}

// ---------------- tf32 GEMM: C[M,N] = A[M,K] @ W[N,K]^T + bias ----------------
__global__ __launch_bounds__(256)
void gemm_tf32_kernel(const float* __restrict__ A, const float* __restrict__ W,
                      const float* __restrict__ bias, float* __restrict__ C,
                      int M, int N, int K) {
    __shared__ unsigned As[2][16][SPITCH];
    __shared__ unsigned Bs[2][16][SPITCH];
    const int tid = threadIdx.x;
    const int wid = tid >> 5, lane = tid & 31;
    const int grp = lane >> 2, tig = lane & 3;
    const int wm = wid & 1, wn = wid >> 1;        // 2 x 4 warps -> 64 x 32 warp tile
    const int m0 = blockIdx.y * 128, n0 = blockIdx.x * 128;
    const int row = tid >> 1, colh = (tid & 1) * 8;
    const float* Ap = A + (size_t)(m0 + row) * K + colh;
    const float* Wp = W + (size_t)(n0 + row) * K + colh;
    float acc[4][4][4] = {};
    const int T = K >> 4;
    float4 av0 = *(const float4*)Ap,        av1 = *(const float4*)(Ap + 4);
    float4 wv0 = *(const float4*)Wp,        wv1 = *(const float4*)(Wp + 4);
    int buf = 0;
    for (int t = 0; t < T; t++) {
        As[buf][colh+0][row] = f2tf(av0.x); As[buf][colh+1][row] = f2tf(av0.y);
        As[buf][colh+2][row] = f2tf(av0.z); As[buf][colh+3][row] = f2tf(av0.w);
        As[buf][colh+4][row] = f2tf(av1.x); As[buf][colh+5][row] = f2tf(av1.y);
        As[buf][colh+6][row] = f2tf(av1.z); As[buf][colh+7][row] = f2tf(av1.w);
        Bs[buf][colh+0][row] = f2tf(wv0.x); Bs[buf][colh+1][row] = f2tf(wv0.y);
        Bs[buf][colh+2][row] = f2tf(wv0.z); Bs[buf][colh+3][row] = f2tf(wv0.w);
        Bs[buf][colh+4][row] = f2tf(wv1.x); Bs[buf][colh+5][row] = f2tf(wv1.y);
        Bs[buf][colh+6][row] = f2tf(wv1.z); Bs[buf][colh+7][row] = f2tf(wv1.w);
        __syncthreads();
        if (t + 1 < T) {
            av0 = *(const float4*)(Ap + (t+1)*16); av1 = *(const float4*)(Ap + (t+1)*16 + 4);
            wv0 = *(const float4*)(Wp + (t+1)*16); wv1 = *(const float4*)(Wp + (t+1)*16 + 4);
        }
        #pragma unroll
        for (int ks = 0; ks < 2; ks++) {
            const int k0 = ks * 8;
            unsigned af[4][4], bf[4][2];
            #pragma unroll
            for (int mi = 0; mi < 4; mi++) {
                int m = wm*64 + mi*16;
                af[mi][0] = As[buf][k0+tig  ][m+grp];
                af[mi][1] = As[buf][k0+tig  ][m+grp+8];
                af[mi][2] = As[buf][k0+tig+4][m+grp];
                af[mi][3] = As[buf][k0+tig+4][m+grp+8];
            }
            #pragma unroll
            for (int ni = 0; ni < 4; ni++) {
                int n = wn*32 + ni*8;
                bf[ni][0] = Bs[buf][k0+tig  ][n+grp];
                bf[ni][1] = Bs[buf][k0+tig+4][n+grp];
            }
            #pragma unroll
            for (int mi = 0; mi < 4; mi++)
                #pragma unroll
                for (int ni = 0; ni < 4; ni++)
                    mma_tf32(acc[mi][ni], af[mi][0], af[mi][1], af[mi][2], af[mi][3],
                             bf[ni][0], bf[ni][1]);
        }
        buf ^= 1;
    }
    #pragma unroll
    for (int mi = 0; mi < 4; mi++) {
        int m = m0 + wm*64 + mi*16 + grp;
        #pragma unroll
        for (int ni = 0; ni < 4; ni++) {
            int n = n0 + wn*32 + ni*8 + 2*tig;
            float b0 = bias[n], b1 = bias[n+1];
            float2 o;
            o.x = acc[mi][ni][0] + b0; o.y = acc[mi][ni][1] + b1;
            *(float2*)&C[(size_t)m * N + n] = o;
            o.x = acc[mi][ni][2] + b0; o.y = acc[mi][ni][3] + b1;
            *(float2*)&C[(size_t)(m+8) * N + n] = o;
        }
    }
}

// ---------------- tf32 scores: (q.k)/sqrt(HD) + mask ----------------
__global__ __launch_bounds__(256)
void scores_tf32_kernel(const unsigned char* __restrict__ mask) {
    const int bh = blockIdx.z, b = bh >> 4, h = bh & 15;
    __shared__ unsigned As[2][16][SPITCH];
    __shared__ unsigned Bs[2][16][SPITCH];
    const int tid = threadIdx.x;
    const int wid = tid >> 5, lane = tid & 31;
    const int grp = lane >> 2, tig = lane & 3;
    const int wm = wid & 1, wn = wid >> 1;
    const int q0 = blockIdx.y * 128, k0g = blockIdx.x * 128;
    const int row = tid >> 1, colh = (tid & 1) * 8;
    const float* Ap = g_qp + (size_t)(b*LQ + q0 + row) * EE + h*HD + colh;
    const float* Bp = g_kp + (size_t)(b*LK + k0g + row) * EE + h*HD + colh;
    float acc[4][4][4] = {};
    float4 av0 = *(const float4*)Ap, av1 = *(const float4*)(Ap + 4);
    float4 wv0 = *(const float4*)Bp, wv1 = *(const float4*)(Bp + 4);
    int buf = 0;
    #pragma unroll
    for (int t = 0; t < 3; t++) {       // K = 48 = 3 * 16
        As[buf][colh+0][row] = f2tf(av0.x); As[buf][colh+1][row] = f2tf(av0.y);
        As[buf][colh+2][row] = f2tf(av0.z); As[buf][colh+3][row] = f2tf(av0.w);
        As[buf][colh+4][row] = f2tf(av1.x); As[buf][colh+5][row] = f2tf(av1.y);
        As[buf][colh+6][row] = f2tf(av1.z); As[buf][colh+7][row] = f2tf(av1.w);
        Bs[buf][colh+0][row] = f2tf(wv0.x); Bs[buf][colh+1][row] = f2tf(wv0.y);
        Bs[buf][colh+2][row] = f2tf(wv0.z); Bs[buf][colh+3][row] = f2tf(wv0.w);
        Bs[buf][colh+4][row] = f2tf(wv1.x); Bs[buf][colh+5][row] = f2tf(wv1.y);
        Bs[buf][colh+6][row] = f2tf(wv1.z); Bs[buf][colh+7][row] = f2tf(wv1.w);
        __syncthreads();
        if (t + 1 < 3) {
            av0 = *(const float4*)(Ap + (t+1)*16); av1 = *(const float4*)(Ap + (t+1)*16 + 4);
            wv0 = *(const float4*)(Bp + (t+1)*16); wv1 = *(const float4*)(Bp + (t+1)*16 + 4);
        }
        #pragma unroll
        for (int ks = 0; ks < 2; ks++) {
            const int k0 = ks * 8;
            unsigned af[4][4], bf[4][2];
            #pragma unroll
            for (int mi = 0; mi < 4; mi++) {
                int m = wm*64 + mi*16;
                af[mi][0] = As[buf][k0+tig  ][m+grp];
                af[mi][1] = As[buf][k0+tig  ][m+grp+8];
                af[mi][2] = As[buf][k0+tig+4][m+grp];
                af[mi][3] = As[buf][k0+tig+4][m+grp+8];
            }
            #pragma unroll
            for (int ni = 0; ni < 4; ni++) {
                int n = wn*32 + ni*8;
                bf[ni][0] = Bs[buf][k0+tig  ][n+grp];
                bf[ni][1] = Bs[buf][k0+tig+4][n+grp];
            }
            #pragma unroll
            for (int mi = 0; mi < 4; mi++)
                #pragma unroll
                for (int ni = 0; ni < 4; ni++)
                    mma_tf32(acc[mi][ni], af[mi][0], af[mi][1], af[mi][2], af[mi][3],
                             bf[ni][0], bf[ni][1]);
        }
        buf ^= 1;
    }
    const float scale = 0.14433756729740643f;
    float* sbase = g_scores + (size_t)bh * LQ * LK;
    const unsigned char* mb = mask + b*LK;
    #pragma unroll
    for (int mi = 0; mi < 4; mi++) {
        int q = q0 + wm*64 + mi*16 + grp;
        #pragma unroll
        for (int ni = 0; ni < 4; ni++) {
            int k = k0g + wn*32 + ni*8 + 2*tig;
            bool m0b = mb[k], m1b = mb[k+1];
            float2 o;
            o.x = m0b ? -1e30f : acc[mi][ni][0] * scale;
            o.y = m1b ? -1e30f : acc[mi][ni][1] * scale;
            *(float2*)&sbase[(size_t)q * LK + k] = o;
            o.x = m0b ? -1e30f : acc[mi][ni][2] * scale;
            o.y = m1b ? -1e30f : acc[mi][ni][3] * scale;
            *(float2*)&sbase[(size_t)(q+8) * LK + k] = o;
        }
    }
}

// ---------------- per-row softmax stats (max, 1/sum) ----------------
__global__ __launch_bounds__(256)
void rowstat_kernel() {
    int row = blockIdx.x;
    const float4* p = (const float4*)(g_scores + (size_t)row * LK);
    int tid = threadIdx.x;
    float4 v0 = p[tid];
    float4 v1 = p[tid + 256];
    float vmax = fmaxf(fmaxf(fmaxf(v0.x, v0.y), fmaxf(v0.z, v0.w)),
                       fmaxf(fmaxf(v1.x, v1.y), fmaxf(v1.z, v1.w)));
    __shared__ float sb[8], sb2[8];
    #pragma unroll
    for (int o = 16; o > 0; o >>= 1) vmax = fmaxf(vmax, __shfl_xor_sync(0xffffffffu, vmax, o));
    if ((tid & 31) == 0) sb[tid >> 5] = vmax;
    __syncthreads();
    float m = sb[0];
    #pragma unroll
    for (int i = 1; i < 8; i++) m = fmaxf(m, sb[i]);
    float s = __expf(v0.x - m) + __expf(v0.y - m) + __expf(v0.z - m) + __expf(v0.w - m)
            + __expf(v1.x - m) + __expf(v1.y - m) + __expf(v1.z - m) + __expf(v1.w - m);
    #pragma unroll
    for (int o = 16; o > 0; o >>= 1) s += __shfl_xor_sync(0xffffffffu, s, o);
    if ((tid & 31) == 0) sb2[tid >> 5] = s;
    __syncthreads();
    if (tid == 0) {
        float tot = 0.f;
        #pragma unroll
        for (int i = 0; i < 8; i++) tot += sb2[i];
        g_rowm[row] = m;
        g_rowinv[row] = 1.f / tot;
    }
}

// ---------------- tf32 ctx: softmax-normalize on the fly, P @ V ----------------
__global__ __launch_bounds__(256)
void ctx_tf32_kernel() {
    const int bh = blockIdx.y, b = bh >> 4, h = bh & 15;
    const int q0 = blockIdx.x * 128;
    __shared__ unsigned As[32][SPITCH];
    __shared__ unsigned Vs[32][56];
    const int tid = threadIdx.x;
    const int wid = tid >> 5, lane = tid & 31;
    const int grp = lane >> 2, tig = lane & 3;
    const int row = tid >> 1, kc = (tid & 1) * 16;
    const float* srow = g_scores + ((size_t)bh * LQ + q0) * LK;
    const float* vbase = g_vp + (size_t)b * LK * EE + h * HD;
    const float rm  = g_rowm[bh*LQ + q0 + row];
    const float rin = g_rowinv[bh*LQ + q0 + row];
    float acc[6][4] = {};
    for (int kb = 0; kb < LK; kb += 32) {
        const float4* sp = (const float4*)(srow + (size_t)row * LK + kb + kc);
        #pragma unroll
        for (int c4 = 0; c4 < 4; c4++) {
            float4 v = sp[c4];
            int kk = kc + c4*4;
            As[kk+0][row] = f2tf(__expf(v.x - rm) * rin);
            As[kk+1][row] = f2tf(__expf(v.y - rm) * rin);
            As[kk+2][row] = f2tf(__expf(v.z - rm) * rin);
            As[kk+3][row] = f2tf(__expf(v.w - rm) * rin);
        }
        #pragma unroll
        for (int i = tid; i < 32*48; i += 256) {
            int kk = i / 48, d = i - kk*48;
            Vs[kk][d] = f2tf(vbase[(size_t)(kb + kk) * EE + d]);
        }
        __syncthreads();
        const int m = wid * 16;
        #pragma unroll
        for (int ks = 0; ks < 4; ks++) {
            const int k0 = ks * 8;
            unsigned a0 = As[k0+tig  ][m+grp];
            unsigned a1 = As[k0+tig  ][m+grp+8];
            unsigned a2 = As[k0+tig+4][m+grp];
            unsigned a3 = As[k0+tig+4][m+grp+8];
            #pragma unroll
            for (int ni = 0; ni < 6; ni++) {
                unsigned b0 = Vs[k0+tig  ][ni*8+grp];
                unsigned b1 = Vs[k0+tig+4][ni*8+grp];
                mma_tf32(acc[ni], a0, a1, a2, a3, b0, b1);
            }
        }
        __syncthreads();
    }
    float* cb = g_ctx + (size_t)(b*LQ + q0 + wid*16) * EE + h*HD;
    #pragma unroll
    for (int ni = 0; ni < 6; ni++) {
        int d = ni*8 + 2*tig;
        float2 o;
        o.x = acc[ni][0]; o.y = acc[ni][1];
        *(float2*)&cb[(size_t)grp * EE + d] = o;
        o.x = acc[ni][2]; o.y = acc[ni][3];
        *(float2*)&cb[(size_t)(grp+8) * EE + d] = o;
    }
}

// ---------------- attn_weights = head mean of normalized probs ----------------
__global__ void attnmean_kernel(float* __restrict__ aw) {
    size_t idx = (size_t)blockIdx.x * blockDim.x + threadIdx.x;
    const size_t nPer = (size_t)LQ * (LK/4);
    if (idx >= (size_t)BB * nPer) return;
    size_t b = idx / nPer, rem = idx % nPer;
    int q = (int)(rem / (LK/4));
    size_t k4 = rem % (LK/4);
    const float4* base = (const float4*)g_scores;
    float4 s = make_float4(0.f, 0.f, 0.f, 0.f);
    #pragma unroll
    for (int h = 0; h < HH; h++) {
        int row = ((int)b*HH + h)*LQ + q;
        float m = g_rowm[row], inv = g_rowinv[row];
        float4 v = base[(size_t)row * (LK/4) + k4];
        s.x += __expf(v.x - m) * inv;
        s.y += __expf(v.y - m) * inv;
        s.z += __expf(v.z - m) * inv;
        s.w += __expf(v.w - m) * inv;
    }
    const float invH = 1.f / (float)HH;
    s.x *= invH; s.y *= invH; s.z *= invH; s.w *= invH;
    ((float4*)aw)[idx] = s;
}

// ---------------- gate + residual + LayerNorm ----------------
__global__ __launch_bounds__(256)
void final_kernel(const float* __restrict__ query, const float* __restrict__ ln_g,
                  const float* __restrict__ ln_b, float* __restrict__ out) {
    int row = blockIdx.x;
    int b = row / LQ;
    float sf = g_sf[b], gv = g_gv[b];
    const float* qrow = query + (size_t)row * EE;
    const float* arow = g_attnout + (size_t)row * EE;
    __shared__ float sx[EE];
    __shared__ float sbuf[8], sbuf2[8];
    int tid = threadIdx.x;
    float lsum = 0.f, lsq = 0.f;
    for (int i = tid; i < EE; i += 256) {
        float qv = qrow[i];
        float gated = qv * (1.f - gv) + arow[i] * sf * gv;
        float x = qv + gated;
        sx[i] = x; lsum += x; lsq += x * x;
    }
    #pragma unroll
    for (int o = 16; o > 0; o >>= 1) {
        lsum += __shfl_xor_sync(0xffffffffu, lsum, o);
        lsq  += __shfl_xor_sync(0xffffffffu, lsq, o);
    }
    if ((tid & 31) == 0) { sbuf[tid >> 5] = lsum; sbuf2[tid >> 5] = lsq; }
    __syncthreads();
    float ts = 0.f, tq = 0.f;
    #pragma unroll
    for (int i = 0; i < 8; i++) { ts += sbuf[i]; tq += sbuf2[i]; }
    float mu = ts / (float)EE;
    float var = tq / (float)EE - mu * mu;
    float inv = rsqrtf(var + 1e-5f);
    float* orow = out + (size_t)row * EE;
    for (int i = tid; i < EE; i += 256)
        orow[i] = (sx[i] - mu) * inv * ln_g[i] + ln_b[i];
}

// ---------------- launch ----------------
extern "C" void kernel_launch(void* const* d_in, const int* in_sizes, int n_in,
                              void* d_out, int out_size) {
    const float* query = (const float*)d_in[0];
    const float* key   = (const float*)d_in[1];
    const float* value = (const float*)d_in[2];
    const unsigned char* mask = (const unsigned char*)d_in[3];
    const float* Wp1 = (const float*)d_in[4];
    const float* bp1 = (const float*)d_in[5];
    const float* Wp2 = (const float*)d_in[6];
    const float* bp2 = (const float*)d_in[7];
    const float* Wp3 = (const float*)d_in[8];
    const float* bp3 = (const float*)d_in[9];
    const float* inw = (const float*)d_in[10];
    const float* inb = (const float*)d_in[11];
    const float* outw = (const float*)d_in[12];
    const float* outb = (const float*)d_in[13];
    const float* lng = (const float*)d_in[14];
    const float* lnb = (const float*)d_in[15];

    float* out = (float*)d_out;
    float* out_output = out;
    float* out_aw = out + (size_t)BB * LQ * EE;
    float* out_tail = out_aw + (size_t)BB * LQ * LK;

    float *qp, *kp, *vp, *ctx, *aout;
    cudaGetSymbolAddress((void**)&qp, g_qp);
    cudaGetSymbolAddress((void**)&kp, g_kp);
    cudaGetSymbolAddress((void**)&vp, g_vp);
    cudaGetSymbolAddress((void**)&ctx, g_ctx);
    cudaGetSymbolAddress((void**)&aout, g_attnout);

    mean_kernel<<<(BB*EE + 255)/256, 256>>>(query, LQ, 0);
    mean_kernel<<<(BB*EE + 255)/256, 256>>>(key,   LK, 1);
    mlp_kernel<<<BB, EE>>>(Wp1, bp1, Wp2, bp2, Wp3, bp3, out_tail);

    gemm_tf32_kernel<<<dim3(EE/128, MQ/128), 256>>>(query, inw,           inb,        qp,  MQ, EE, EE);
    gemm_tf32_kernel<<<dim3(EE/128, MK/128), 256>>>(key,   inw + EE*EE,   inb + EE,   kp,  MK, EE, EE);
    gemm_tf32_kernel<<<dim3(EE/128, MK/128), 256>>>(value, inw + 2*EE*EE, inb + 2*EE, vp,  MK, EE, EE);

    scores_tf32_kernel<<<dim3(LK/128, LQ/128, BB*HH), 256>>>(mask);
    rowstat_kernel<<<BB*HH*LQ, 256>>>();
    ctx_tf32_kernel<<<dim3(LQ/128, BB*HH), 256>>>();

    gemm_tf32_kernel<<<dim3(EE/128, MQ/128), 256>>>(ctx, outw, outb, aout, MQ, EE, EE);

    {
        size_t n4 = (size_t)BB * LQ * LK / 4;
        attnmean_kernel<<<(unsigned)((n4 + 255)/256), 256>>>(out_aw);
    }
    final_kernel<<<BB*LQ, 256>>>(query, lng, lnb, out_output);
}